// round 10
// baseline (speedup 1.0000x reference)
#include <cuda_runtime.h>

// out[b, 0, h, w] = 0.5f * (x[b,0,h,w] + x[b,1,h,w] + x[b,2,h,w])
// Exact algebraic collapse of the diagonal Haar decompose + reconstruct:
//   recon(0::2,1::2) = 0.5*(up_low+up_det) = 0.5*sum_c x01
//   recon(1::2,0::2) = 0.5*(up_low-up_det) = 0.5*sum_c x10
//   recon(0::2,0::2) = 0.5*(dn_low+dn_det) = 0.5*sum_c x00
//   recon(1::2,1::2) = 0.5*(dn_low-dn_det) = 0.5*sum_c x11
// i.e. every output pixel = 0.5 * channel-sum at the same spatial location.
//
// FINAL (measured optimum, 9 rounds). HBM roofline: 268.4 MB irreducible
// traffic @ 7.2-7.4 TB/s effective (90-93% of 8 TB/s spec). Identical-binary
// noise band: kernel 36.19-37.47 us, bench 41.44-42.69 us.
//   R1 MLP=3, 4M threads        36.83 us
//   R2 MLP=6 adjacent + ldcs    36.83 us
//   R3/R5/R7/R9 MLP=6 strided   36.19-37.47 us   <- this kernel
//   R4 MLP=12, 1M threads       38.21 us (thread population down -> DRAM% down)
//   R6 v8.b32 256-bit           37.73 us (neutral)
//   R8 persistent 592 blocks    39.20 us (thread population down -> DRAM% down)
// Confirmed real effects: maximize thread population (2M), keep every warp
// LDG.128 a contiguous 512B access. All other axes (access width, cache
// hints, scheduling shape) measured flat.

static constexpr int B = 16;
static constexpr int C = 3;
static constexpr long long HW = 1024LL * 1024LL;            // elems per plane (2^20)
static constexpr long long OUT_ELEMS = (long long)B * HW;   // 16,777,216
static constexpr long long OUT_VECS = OUT_ELEMS / 4;        // 4,194,304 float4s
static constexpr int THREADS = 512;
static constexpr int VPT = 2;                               // float4s per thread
static constexpr long long VECS_PER_BLOCK = (long long)THREADS * VPT;   // 1024
static constexpr int GRID = (int)(OUT_VECS / VECS_PER_BLOCK);           // 4096

__global__ void __launch_bounds__(THREADS) haar_chansum_kernel(
    const float* __restrict__ x, float* __restrict__ out) {
    // Thread handles vecs v0 and v0 + THREADS; the block's 1024-vec (4096-elem)
    // chunk never crosses a plane boundary (HW/4 = 262144 is a multiple of 1024).
    long long v0 = (long long)blockIdx.x * VECS_PER_BLOCK + threadIdx.x;
    long long e0 = v0 * 4;                  // element index of first float4
    long long b  = e0 >> 20;                // batch (HW = 2^20)
    long long p  = e0 & (HW - 1);           // pixel within plane
    const float* base = x + (b * C) * HW + p;

    const float4* c0 = reinterpret_cast<const float4*>(base);
    const float4* c1 = reinterpret_cast<const float4*>(base + HW);
    const float4* c2 = reinterpret_cast<const float4*>(base + 2LL * HW);

    // 6 independent, fully-coalesced LDG.128 (each warp access = 512B contiguous)
    float4 a0 = c0[0];
    float4 a1 = c1[0];
    float4 a2 = c2[0];
    float4 b0 = c0[THREADS];
    float4 b1 = c1[THREADS];
    float4 b2 = c2[THREADS];

    float4 r0, r1;
    r0.x = 0.5f * (a0.x + a1.x + a2.x);
    r0.y = 0.5f * (a0.y + a1.y + a2.y);
    r0.z = 0.5f * (a0.z + a1.z + a2.z);
    r0.w = 0.5f * (a0.w + a1.w + a2.w);
    r1.x = 0.5f * (b0.x + b1.x + b2.x);
    r1.y = 0.5f * (b0.y + b1.y + b2.y);
    r1.z = 0.5f * (b0.z + b1.z + b2.z);
    r1.w = 0.5f * (b0.w + b1.w + b2.w);

    float4* o = reinterpret_cast<float4*>(out + e0);
    __stcs(o + 0, r0);
    __stcs(o + THREADS, r1);
}

extern "C" void kernel_launch(void* const* d_in, const int* in_sizes, int n_in,
                              void* d_out, int out_size) {
    const float* x = (const float*)d_in[0];
    float* out = (float*)d_out;
    haar_chansum_kernel<<<GRID, THREADS>>>(x, out);
}